// round 17
// baseline (speedup 1.0000x reference)
#include <cuda_runtime.h>
#include <cuda_bf16.h>
#include <math.h>
#include <stdint.h>

#define SEQ 4096
#define DIM 1024
#define RMS_EPS 1.1920929e-7f  // jnp.finfo(float32).eps

// ======================= device scratch (alloc-free rule) =======================
#define AL __device__ __align__(16)
AL __nv_bfloat16 g_h_hi[SEQ * DIM],  g_h_lo[SEQ * DIM];
AL __nv_bfloat16 g_wq_hi[DIM * DIM], g_wq_lo[DIM * DIM];
AL __nv_bfloat16 g_wk_hi[DIM * DIM], g_wk_lo[DIM * DIM];
AL __nv_bfloat16 g_wv_hi[DIM * DIM], g_wv_lo[DIM * DIM];
AL __nv_bfloat16 g_q_hi[SEQ * DIM],  g_q_lo[SEQ * DIM];
AL __nv_bfloat16 g_k_hi[SEQ * DIM],  g_k_lo[SEQ * DIM];
AL __nv_bfloat16 g_vt_hi[DIM * SEQ], g_vt_lo[DIM * SEQ];   // V^T [DIM, SEQ]
AL float         g_logits[(size_t)SEQ * SEQ];
AL __nv_bfloat16 g_p_hi[(size_t)SEQ * SEQ], g_p_lo[(size_t)SEQ * SEQ];

// ---- work-queue state (reset by prep_kernel every launch/replay) ----
__device__ int g_ctr;
__device__ int g_qr[32];   // q row-blocks ready (count to 8)
__device__ int g_kr[32];   // k row-blocks ready (count to 8)
__device__ int g_ld[32];   // logits row-blocks done (count to 32)
__device__ int g_pr[32];   // softmax P row-blocks ready (flag)
__device__ int g_vd;       // v tiles done (count to 256)

// item layout: [0,768) qkv | [768,1792) logits | [1792,1824) softmax | [1824,2080) pv
#define N_QKV   768
#define N_LOGI  1024
#define N_SOFT  32
#define N_PV    256
#define NITEMS  (N_QKV + N_LOGI + N_SOFT + N_PV)

// ======================= PTX helpers (base sm_103 target — no 'a' features) ==========
__device__ __forceinline__ uint32_t smem_u32(const void* p) {
    uint32_t a;
    asm("{ .reg .u64 t; cvta.to.shared.u64 t, %1; cvt.u32.u64 %0, t; }" : "=r"(a) : "l"(p));
    return a;
}
__device__ __forceinline__ void cp16(uint32_t dst, const void* src) {
    asm volatile("cp.async.cg.shared.global [%0], [%1], 16;" :: "r"(dst), "l"(src));
}
#define CP_COMMIT() asm volatile("cp.async.commit_group;" ::: "memory")
#define CP_WAIT1()  asm volatile("cp.async.wait_group 1;" ::: "memory")

__device__ __forceinline__ void ldsm_x4(uint32_t* r, uint32_t addr) {
    asm volatile("ldmatrix.sync.aligned.m8n8.x4.shared.b16 {%0,%1,%2,%3}, [%4];"
        : "=r"(r[0]), "=r"(r[1]), "=r"(r[2]), "=r"(r[3]) : "r"(addr) : "memory");
}
__device__ __forceinline__ void mma_bf16(float* c, const uint32_t* a, const uint32_t* b) {
    asm volatile(
        "mma.sync.aligned.m16n8k16.row.col.f32.bf16.bf16.f32 "
        "{%0,%1,%2,%3}, {%4,%5,%6,%7}, {%8,%9}, {%0,%1,%2,%3};"
        : "+f"(c[0]), "+f"(c[1]), "+f"(c[2]), "+f"(c[3])
        : "r"(a[0]), "r"(a[1]), "r"(a[2]), "r"(a[3]), "r"(b[0]), "r"(b[1]));
}

// ======================= fast math (FMA-pipe, no MUFU) =======================
__device__ __forceinline__ float fast_exp(float x) {
    float t = x * 1.4426950408889634f;
    t = fmaxf(fminf(t, 125.0f), -125.0f);
    float r = t + 12582912.0f;
    int   n = __float_as_int(r) - 0x4B400000;
    float f = t - (r - 12582912.0f);
    float p = 1.5403530393381609e-4f;
    p = fmaf(p, f, 1.3333558146428443e-3f);
    p = fmaf(p, f, 9.6181291076284772e-3f);
    p = fmaf(p, f, 5.5504108664821580e-2f);
    p = fmaf(p, f, 2.4022650695910072e-1f);
    p = fmaf(p, f, 6.9314718055994531e-1f);
    p = fmaf(p, f, 1.0f);
    return __int_as_float(__float_as_int(p) + (n << 23));
}
__device__ __forceinline__ float fast_rcp(float y) {
    float r = __int_as_float(0x7EF311C3 - __float_as_int(y));
    r = r * (2.0f - y * r);
    r = r * (2.0f - y * r);
    r = r * (2.0f - y * r);
    return r;
}
__device__ __forceinline__ float fast_silu(float v) {
    float e = fast_exp(-v);
    return v * fast_rcp(1.0f + e);
}

// ======================= split helper =======================
__device__ __forceinline__ void split1(float a, __nv_bfloat16& hi, __nv_bfloat16& lo) {
    hi = __float2bfloat16(a);
    lo = __float2bfloat16(a - __bfloat162float(hi));
}

// ======================= block reductions (prep kernel, 256 thr) ===================
__device__ __forceinline__ float block_reduce_sum(float val) {
    __shared__ float sh[32];
    __syncthreads();
    int lane = threadIdx.x & 31, wid = threadIdx.x >> 5;
    #pragma unroll
    for (int o = 16; o > 0; o >>= 1) val += __shfl_down_sync(0xffffffffu, val, o);
    if (lane == 0) sh[wid] = val;
    __syncthreads();
    int nw = (blockDim.x + 31) >> 5;
    val = (threadIdx.x < nw) ? sh[threadIdx.x] : 0.0f;
    if (wid == 0) {
        #pragma unroll
        for (int o = 16; o > 0; o >>= 1) val += __shfl_down_sync(0xffffffffu, val, o);
        if (lane == 0) sh[0] = val;
    }
    __syncthreads();
    return sh[0];
}

// ======================= fused prep: flags reset + embed+RMSNorm + weight splits =====
#define WBLK (DIM * DIM / 4 / 256)   // 1024 blocks per weight
__global__ void __launch_bounds__(256) prep_kernel(
    const int* __restrict__ x, const float* __restrict__ emb,
    const float* __restrict__ norm_w,
    __nv_bfloat16* __restrict__ hhi, __nv_bfloat16* __restrict__ hlo,
    const float4* __restrict__ Wq, const float4* __restrict__ Wk, const float4* __restrict__ Wv,
    __nv_bfloat162* __restrict__ ah, __nv_bfloat162* __restrict__ al,
    __nv_bfloat162* __restrict__ bh, __nv_bfloat162* __restrict__ bl,
    __nv_bfloat162* __restrict__ ch, __nv_bfloat162* __restrict__ cl)
{
    if (blockIdx.x == 0) {
        if (threadIdx.x == 0) { g_ctr = 0; g_vd = 0; }
        if (threadIdx.x < 32) {
            g_qr[threadIdx.x] = 0; g_kr[threadIdx.x] = 0;
            g_ld[threadIdx.x] = 0; g_pr[threadIdx.x] = 0;
        }
    }
    if (blockIdx.x < SEQ) {
        int s = blockIdx.x;
        int row = x[s];
        const float4* e4 = reinterpret_cast<const float4*>(emb + (size_t)row * DIM);
        const float4* w4 = reinterpret_cast<const float4*>(norm_w);

        float4 v = e4[threadIdx.x];
        float ss = v.x * v.x + v.y * v.y + v.z * v.z + v.w * v.w;
        ss = block_reduce_sum(ss);
        float scale = rsqrtf(ss * (1.0f / DIM) + RMS_EPS);
        float4 w = w4[threadIdx.x];
        float o[4];
        o[0] = v.x * scale * w.x; o[1] = v.y * scale * w.y;
        o[2] = v.z * scale * w.z; o[3] = v.w * scale * w.w;

        __nv_bfloat162* ph = reinterpret_cast<__nv_bfloat162*>(hhi + (size_t)s * DIM);
        __nv_bfloat162* pl = reinterpret_cast<__nv_bfloat162*>(hlo + (size_t)s * DIM);
        #pragma unroll
        for (int i = 0; i < 2; i++) {
            __nv_bfloat162 h2, l2;
            split1(o[2 * i],     h2.x, l2.x);
            split1(o[2 * i + 1], h2.y, l2.y);
            ph[threadIdx.x * 2 + i] = h2;
            pl[threadIdx.x * 2 + i] = l2;
        }
    } else {
        int b = blockIdx.x - SEQ;
        int which = b / WBLK;
        int i = (b % WBLK) * 256 + threadIdx.x;
        const float4* src = (which == 0) ? Wq : (which == 1) ? Wk : Wv;
        __nv_bfloat162* hi = (which == 0) ? ah : (which == 1) ? bh : ch;
        __nv_bfloat162* lo = (which == 0) ? al : (which == 1) ? bl : cl;
        float4 v = src[i];
        __nv_bfloat162 h0, l0, h1, l1;
        split1(v.x, h0.x, l0.x); split1(v.y, h0.y, l0.y);
        split1(v.z, h1.x, l1.x); split1(v.w, h1.y, l1.y);
        hi[2 * i] = h0; hi[2 * i + 1] = h1;
        lo[2 * i] = l0; lo[2 * i + 1] = l1;
    }
}

// ======================= shared GEMM core (mma.sync bf16-split) =======================
// 128x128 CTA tile, 128 threads, 4 warps in 2x2, warp tile 64x64, 3-stage pipeline.
#define TILE_BYTES 8192
#define STAGE_BYTES (4 * TILE_BYTES)
#define NSTAGE 3
#define GEMM_SMEM (NSTAGE * STAGE_BYTES)

__device__ __forceinline__ uint32_t sw(uint32_t row, uint32_t chunk) {
    return row * 64u + ((chunk ^ ((row >> 1) & 3u)) << 4);
}

__device__ __forceinline__ void load_stage_half(uint32_t sbase,
    const __nv_bfloat16* __restrict__ Ahi, const __nv_bfloat16* __restrict__ Alo,
    const __nv_bfloat16* __restrict__ Bhi, const __nv_bfloat16* __restrict__ Blo,
    size_t arow0, size_t brow0, int K, int k0, int tid, int half)
{
    #pragma unroll
    for (int j = 0; j < 2; j++) {
        int idx = tid + (half * 2 + j) * 128;
        int row = idx >> 2, ch = idx & 3;
        uint32_t so = sw(row, ch);
        size_t goff = (size_t)row * K + k0 + ch * 8;
        cp16(sbase + 0 * TILE_BYTES + so, Ahi + arow0 * K + goff);
        cp16(sbase + 1 * TILE_BYTES + so, Alo + arow0 * K + goff);
        cp16(sbase + 2 * TILE_BYTES + so, Bhi + brow0 * K + goff);
        cp16(sbase + 3 * TILE_BYTES + so, Blo + brow0 * K + goff);
    }
}

__device__ __forceinline__ void gemm_core(uint32_t sbase,
    const __nv_bfloat16* __restrict__ Ahi, const __nv_bfloat16* __restrict__ Alo,
    const __nv_bfloat16* __restrict__ Bhi, const __nv_bfloat16* __restrict__ Blo,
    size_t arow0, size_t brow0, int K, float acc[4][8][4])
{
    const int tid = threadIdx.x, wid = tid >> 5, lid = tid & 31;
    const int wm = wid >> 1, wn = wid & 1;

    const int a_r  = (lid & 7) + ((lid >> 3) & 1) * 8;
    const int a_kb = lid >> 4;
    const int b_r  = (lid & 7) + (lid >> 4) * 8;
    const int b_kb = (lid >> 3) & 1;
    const int nch = K >> 5;

    load_stage_half(sbase, Ahi, Alo, Bhi, Blo, arow0, brow0, K, 0, tid, 0);
    load_stage_half(sbase, Ahi, Alo, Bhi, Blo, arow0, brow0, K, 0, tid, 1);
    CP_COMMIT();
    load_stage_half(sbase + STAGE_BYTES, Ahi, Alo, Bhi, Blo, arow0, brow0, K, 32, tid, 0);
    load_stage_half(sbase + STAGE_BYTES, Ahi, Alo, Bhi, Blo, arow0, brow0, K, 32, tid, 1);
    CP_COMMIT();

    int slot = 0, nslot = 2;
    for (int c = 0; c < nch; c++) {
        CP_WAIT1();
        __syncthreads();
        const uint32_t cur = sbase + (uint32_t)slot * STAGE_BYTES;

        #pragma unroll
        for (int ks = 0; ks < 2; ks++) {
            uint32_t ahi[4][4], alo[4][4];
            #pragma unroll
            for (int mf = 0; mf < 4; mf++) {
                uint32_t arow = (uint32_t)(wm * 64 + mf * 16 + a_r);
                uint32_t ach  = (uint32_t)(ks * 2 + a_kb);
                ldsm_x4(ahi[mf], cur + 0 * TILE_BYTES + sw(arow, ach));
                ldsm_x4(alo[mf], cur + 1 * TILE_BYTES + sw(arow, ach));
            }
            #pragma unroll
            for (int np = 0; np < 4; np++) {
                uint32_t brow = (uint32_t)(wn * 64 + np * 16 + b_r);
                uint32_t bch  = (uint32_t)(ks * 2 + b_kb);
                uint32_t th[4], tl[4];
                ldsm_x4(th, cur + 2 * TILE_BYTES + sw(brow, bch));
                ldsm_x4(tl, cur + 3 * TILE_BYTES + sw(brow, bch));
                uint32_t b0h[2] = { th[0], th[1] }, b1h[2] = { th[2], th[3] };
                uint32_t b0l[2] = { tl[0], tl[1] }, b1l[2] = { tl[2], tl[3] };
                #pragma unroll
                for (int mf = 0; mf < 4; mf++) {
                    mma_bf16(acc[mf][np * 2],     ahi[mf], b0h);
                    mma_bf16(acc[mf][np * 2 + 1], ahi[mf], b1h);
                }
                #pragma unroll
                for (int mf = 0; mf < 4; mf++) {
                    mma_bf16(acc[mf][np * 2],     ahi[mf], b0l);
                    mma_bf16(acc[mf][np * 2 + 1], ahi[mf], b1l);
                }
                #pragma unroll
                for (int mf = 0; mf < 4; mf++) {
                    mma_bf16(acc[mf][np * 2],     alo[mf], b0h);
                    mma_bf16(acc[mf][np * 2 + 1], alo[mf], b1h);
                }
            }
            if (c + 2 < nch)
                load_stage_half(sbase + (uint32_t)nslot * STAGE_BYTES,
                                Ahi, Alo, Bhi, Blo, arow0, brow0, K, (c + 2) * 32, tid, ks);
            if (ks == 1) CP_COMMIT();
        }
        slot = (slot == 2) ? 0 : slot + 1;
        nslot = (nslot == 2) ? 0 : nslot + 1;
    }
    __syncthreads();
}

// ======================= spin-wait (acquire) =======================
__device__ __forceinline__ void wait_ge(volatile int* f, int target) {
    if (threadIdx.x == 0) {
        while (*f < target) __nanosleep(64);
    }
    __syncthreads();
    __threadfence();   // order subsequent reads after flag observation
}

// ======================= persistent mega-kernel =======================
__global__ void __launch_bounds__(128, 2) attn_kernel(float* __restrict__ out)
{
    extern __shared__ char smem[];
    const uint32_t sbase = smem_u32(smem);
    __shared__ int s_item;
    const int tid = threadIdx.x, wid = tid >> 5, lid = tid & 31;
    const int wm = wid >> 1, wn = wid & 1;

    for (;;) {
        __syncthreads();                       // protect s_item reuse
        if (tid == 0) s_item = atomicAdd(&g_ctr, 1);
        __syncthreads();
        const int item = s_item;
        if (item >= NITEMS) return;

        if (item >= N_QKV + N_LOGI && item < N_QKV + N_LOGI + N_SOFT) {
            // ---------------- softmax row-block ----------------
            const int r = item - (N_QKV + N_LOGI);
            wait_ge(&g_ld[r], 32);
            // 4 warps; each warp processes 32 rows, one row at a time
            for (int rr = wid; rr < 128; rr += 4) {
                const size_t row = (size_t)(r * 128 + rr);
                const float4* src = reinterpret_cast<const float4*>(g_logits + row * SEQ);
                float4 v[32];
                float mx = -INFINITY;
                #pragma unroll
                for (int i = 0; i < 32; i++) {
                    v[i] = __ldcg(&src[lid + 32 * i]);
                    mx = fmaxf(mx, fmaxf(fmaxf(v[i].x, v[i].y), fmaxf(v[i].z, v[i].w)));
                }
                #pragma unroll
                for (int o = 16; o > 0; o >>= 1)
                    mx = fmaxf(mx, __shfl_xor_sync(0xffffffffu, mx, o));
                float sum = 0.0f;
                #pragma unroll
                for (int i = 0; i < 32; i++) {
                    v[i].x = fast_exp(v[i].x - mx); v[i].y = fast_exp(v[i].y - mx);
                    v[i].z = fast_exp(v[i].z - mx); v[i].w = fast_exp(v[i].w - mx);
                    sum += v[i].x + v[i].y + v[i].z + v[i].w;
                }
                #pragma unroll
                for (int o = 16; o > 0; o >>= 1)
                    sum += __shfl_xor_sync(0xffffffffu, sum, o);
                float inv = fast_rcp(sum);
                uint2* ph = reinterpret_cast<uint2*>(g_p_hi + row * SEQ);
                uint2* pl = reinterpret_cast<uint2*>(g_p_lo + row * SEQ);
                #pragma unroll
                for (int i = 0; i < 32; i++) {
                    __nv_bfloat162 h0, l0, h1, l1;
                    split1(v[i].x * inv, h0.x, l0.x); split1(v[i].y * inv, h0.y, l0.y);
                    split1(v[i].z * inv, h1.x, l1.x); split1(v[i].w * inv, h1.y, l1.y);
                    uint2 hv, lv;
                    hv.x = *reinterpret_cast<uint32_t*>(&h0); hv.y = *reinterpret_cast<uint32_t*>(&h1);
                    lv.x = *reinterpret_cast<uint32_t*>(&l0); lv.y = *reinterpret_cast<uint32_t*>(&l1);
                    ph[lid + 32 * i] = hv;
                    pl[lid + 32 * i] = lv;
                }
            }
            __syncthreads();
            __threadfence();
            if (tid == 0) atomicExch(&g_pr[r], 1);
            continue;
        }

        // ---------------- GEMM items ----------------
        const __nv_bfloat16 *Ah, *Al, *Bh, *Bl;
        size_t arow0, brow0;
        int K;
        int which = -1, by = 0, r = 0, c = 0, n = 0;

        if (item < N_QKV) {
            which = item >> 8;                   // 0=Q,1=K,2=V
            int sub = item & 255;
            int bxx = sub & 7; by = sub >> 3;
            Ah = g_h_hi; Al = g_h_lo;
            Bh = (which == 0) ? g_wq_hi : (which == 1) ? g_wk_hi : g_wv_hi;
            Bl = (which == 0) ? g_wq_lo : (which == 1) ? g_wk_lo : g_wv_lo;
            arow0 = (size_t)by * 128; brow0 = (size_t)bxx * 128; K = DIM;
        } else if (item < N_QKV + N_LOGI) {
            int t = item - N_QKV;
            r = t >> 5; c = t & 31;
            wait_ge(&g_qr[r], 8);
            wait_ge(&g_kr[c], 8);
            Ah = g_q_hi; Al = g_q_lo; Bh = g_k_hi; Bl = g_k_lo;
            arow0 = (size_t)r * 128; brow0 = (size_t)c * 128; K = DIM;
        } else {
            int t = item - (N_QKV + N_LOGI + N_SOFT);
            r = t >> 3; n = t & 7;
            wait_ge(&g_vd, 256);
            wait_ge(&g_pr[r], 1);
            Ah = g_p_hi; Al = g_p_lo; Bh = g_vt_hi; Bl = g_vt_lo;
            arow0 = (size_t)r * 128; brow0 = (size_t)n * 128; K = SEQ;
        }

        float acc[4][8][4] = {};
        gemm_core(sbase, Ah, Al, Bh, Bl, arow0, brow0, K, acc);

        const int rbase = (int)arow0 + wm * 64 + (lid >> 2);
        const int cbase = (int)brow0 + wn * 64 + (lid & 3) * 2;

        if (item < N_QKV) {
            if (which < 2) {
                __nv_bfloat16* Chi = (which == 0) ? g_q_hi : g_k_hi;
                __nv_bfloat16* Clo = (which == 0) ? g_q_lo : g_k_lo;
                #pragma unroll
                for (int mf = 0; mf < 4; mf++)
                    #pragma unroll
                    for (int nf = 0; nf < 8; nf++)
                        #pragma unroll
                        for (int half = 0; half < 2; half++) {
                            size_t rr = (size_t)(rbase + mf * 16 + half * 8);
                            size_t cc = (size_t)(cbase + nf * 8);
                            __nv_bfloat162 hv, lv;
                            split1(acc[mf][nf][half * 2],     hv.x, lv.x);
                            split1(acc[mf][nf][half * 2 + 1], hv.y, lv.y);
                            *reinterpret_cast<__nv_bfloat162*>(Chi + rr * DIM + cc) = hv;
                            *reinterpret_cast<__nv_bfloat162*>(Clo + rr * DIM + cc) = lv;
                        }
            } else {
                #pragma unroll
                for (int mf = 0; mf < 4; mf++)
                    #pragma unroll
                    for (int nf = 0; nf < 8; nf++)
                        #pragma unroll
                        for (int half = 0; half < 2; half++) {
                            size_t rr = (size_t)(rbase + mf * 16 + half * 8);
                            size_t c0 = (size_t)(cbase + nf * 8);
                            float v0 = acc[mf][nf][half * 2];
                            float v1 = acc[mf][nf][half * 2 + 1];
                            __nv_bfloat16 h0, l0, h1, l1;
                            split1(v0, h0, l0);
                            split1(v1, h1, l1);
                            g_vt_hi[c0 * SEQ + rr] = h0;       g_vt_lo[c0 * SEQ + rr] = l0;
                            g_vt_hi[(c0 + 1) * SEQ + rr] = h1; g_vt_lo[(c0 + 1) * SEQ + rr] = l1;
                        }
            }
            __threadfence();
            if (tid == 0) {
                if (which == 0)      atomicAdd(&g_qr[by], 1);
                else if (which == 1) atomicAdd(&g_kr[by], 1);
                else                 atomicAdd(&g_vd, 1);
            }
        } else if (item < N_QKV + N_LOGI) {
            #pragma unroll
            for (int mf = 0; mf < 4; mf++)
                #pragma unroll
                for (int nf = 0; nf < 8; nf++)
                    #pragma unroll
                    for (int half = 0; half < 2; half++) {
                        size_t rr = (size_t)(rbase + mf * 16 + half * 8);
                        size_t cc = (size_t)(cbase + nf * 8);
                        *reinterpret_cast<float2*>(g_logits + rr * SEQ + cc) =
                            make_float2(acc[mf][nf][half * 2], acc[mf][nf][half * 2 + 1]);
                    }
            __threadfence();
            if (tid == 0) atomicAdd(&g_ld[r], 1);
        } else {
            #pragma unroll
            for (int mf = 0; mf < 4; mf++)
                #pragma unroll
                for (int nf = 0; nf < 8; nf++)
                    #pragma unroll
                    for (int half = 0; half < 2; half++) {
                        size_t rr = (size_t)(rbase + mf * 16 + half * 8);
                        size_t cc = (size_t)(cbase + nf * 8);
                        float v0 = fast_silu(acc[mf][nf][half * 2]);
                        float v1 = fast_silu(acc[mf][nf][half * 2 + 1]);
                        *reinterpret_cast<float2*>(out + rr * DIM + cc) = make_float2(v0, v1);
                    }
        }
    }
}

// ======================= host launch =======================
extern "C" void kernel_launch(void* const* d_in, const int* in_sizes, int n_in,
                              void* d_out, int out_size)
{
    const int*   x      = (const int*)  d_in[0];
    const float* emb    = (const float*)d_in[1];
    const float* norm_w = (const float*)d_in[2];
    const float* Wq     = (const float*)d_in[3];
    const float* Wk     = (const float*)d_in[4];
    const float* Wv     = (const float*)d_in[5];
    float* out = (float*)d_out;

    __nv_bfloat16 *h_hi, *h_lo, *wq_hi, *wq_lo, *wk_hi, *wk_lo, *wv_hi, *wv_lo;
    cudaGetSymbolAddress((void**)&h_hi, g_h_hi);   cudaGetSymbolAddress((void**)&h_lo, g_h_lo);
    cudaGetSymbolAddress((void**)&wq_hi, g_wq_hi); cudaGetSymbolAddress((void**)&wq_lo, g_wq_lo);
    cudaGetSymbolAddress((void**)&wk_hi, g_wk_hi); cudaGetSymbolAddress((void**)&wk_lo, g_wk_lo);
    cudaGetSymbolAddress((void**)&wv_hi, g_wv_hi); cudaGetSymbolAddress((void**)&wv_lo, g_wv_lo);

    cudaFuncSetAttribute((const void*)attn_kernel, cudaFuncAttributeMaxDynamicSharedMemorySize, GEMM_SMEM);

    // 1) prep: flag reset + embed+RMSNorm + weight splits
    prep_kernel<<<SEQ + 3 * WBLK, 256>>>(
        x, emb, norm_w, h_hi, h_lo,
        (const float4*)Wq, (const float4*)Wk, (const float4*)Wv,
        (__nv_bfloat162*)wq_hi, (__nv_bfloat162*)wq_lo,
        (__nv_bfloat162*)wk_hi, (__nv_bfloat162*)wk_lo,
        (__nv_bfloat162*)wv_hi, (__nv_bfloat162*)wv_lo);

    // 2) persistent mega-kernel: QKV -> logits -> softmax -> PV via ordered work queue
    attn_kernel<<<296, 128, GEMM_SMEM>>>(out);
}